// round 2
// baseline (speedup 1.0000x reference)
#include <cuda_runtime.h>
#include <cuda_bf16.h>
#include <cstdint>

#define BB 2
#define NN 4096
#define HH 256
#define NHEADS 4
#define DH 64
#define MTOT (BB*NN)          // 8192 rows

// ---------------------------------------------------------------------------
// Scratch (__device__ globals — no cudaMalloc allowed)
// ---------------------------------------------------------------------------
__device__ float g_Q [(size_t)MTOT * HH];          // 8 MB
__device__ float g_K [(size_t)MTOT * HH];          // 8 MB
__device__ float g_V [(size_t)MTOT * HH];          // 8 MB
__device__ float g_AV[(size_t)MTOT * HH];          // 8 MB
__device__ float g_S [134217728ULL];               // (B*NHEADS*N)*N = 512 MB

#define NEG_INF __int_as_float(0xff800000)

// ---------------------------------------------------------------------------
// GEMM: Y[m,o] = sum_k X[m,k] * W[o,k] + bias[o]
//   X: [M,256] row-major, W: [256,256] row-major, grid (M/64, 256/64), 256 thr
// ---------------------------------------------------------------------------
__global__ __launch_bounds__(256) void gemm_xwt(
    const float* __restrict__ X, const float* __restrict__ W,
    const float* __restrict__ bias, float* __restrict__ Y)
{
    __shared__ float Xs[64 * 65];
    __shared__ float Ws[64 * 65];
    const int tid = threadIdx.x;
    const int tx = tid & 15, ty = tid >> 4;
    const int m0 = blockIdx.x * 64, n0 = blockIdx.y * 64;

    float acc[4][4] = {};

    for (int k0 = 0; k0 < HH; k0 += 64) {
        __syncthreads();
        #pragma unroll
        for (int it = 0; it < 4; it++) {
            int f   = tid + it * 256;      // 0..1023 float4 slots
            int row = f >> 4;
            int dq  = f & 15;
            float4 xv = *(const float4*)&X[(size_t)(m0 + row) * HH + k0 + dq * 4];
            Xs[row * 65 + dq * 4 + 0] = xv.x;
            Xs[row * 65 + dq * 4 + 1] = xv.y;
            Xs[row * 65 + dq * 4 + 2] = xv.z;
            Xs[row * 65 + dq * 4 + 3] = xv.w;
            float4 wv = *(const float4*)&W[(size_t)(n0 + row) * HH + k0 + dq * 4];
            Ws[row * 65 + dq * 4 + 0] = wv.x;
            Ws[row * 65 + dq * 4 + 1] = wv.y;
            Ws[row * 65 + dq * 4 + 2] = wv.z;
            Ws[row * 65 + dq * 4 + 3] = wv.w;
        }
        __syncthreads();
        #pragma unroll 8
        for (int k = 0; k < 64; k++) {
            float a[4], b[4];
            #pragma unroll
            for (int ii = 0; ii < 4; ii++) a[ii] = Xs[(ty * 4 + ii) * 65 + k];
            #pragma unroll
            for (int jj = 0; jj < 4; jj++) b[jj] = Ws[(tx * 4 + jj) * 65 + k];
            #pragma unroll
            for (int ii = 0; ii < 4; ii++)
                #pragma unroll
                for (int jj = 0; jj < 4; jj++)
                    acc[ii][jj] = fmaf(a[ii], b[jj], acc[ii][jj]);
        }
    }

    float4 bv = *(const float4*)&bias[n0 + tx * 4];
    #pragma unroll
    for (int ii = 0; ii < 4; ii++) {
        float4 o;
        o.x = acc[ii][0] + bv.x;
        o.y = acc[ii][1] + bv.y;
        o.z = acc[ii][2] + bv.z;
        o.w = acc[ii][3] + bv.w;
        *(float4*)&Y[(size_t)(m0 + ty * 4 + ii) * HH + n0 + tx * 4] = o;
    }
}

// ---------------------------------------------------------------------------
// Scores: S[b,h,i,j] = (Q_h[i] . K_h[j]) / 8 + tau_i*tau_j*cw[h] + cb[h],
//         masked to -inf where adj[i,j]==0.
// grid (N/64, N/64, B*NHEADS), 256 thr
// ---------------------------------------------------------------------------
__global__ __launch_bounds__(256) void scores_kernel(
    const float* __restrict__ tau, const int* __restrict__ adj,
    const float* __restrict__ cw, const float* __restrict__ cb)
{
    __shared__ float As[64 * 65];
    __shared__ float Bs[64 * 65];
    const int tid = threadIdx.x;
    const int tx = tid & 15, ty = tid >> 4;
    const int bh = blockIdx.z;
    const int b = bh >> 2, h = bh & 3;
    const int i0 = blockIdx.y * 64, j0 = blockIdx.x * 64;

    const float* Qb = g_Q + (size_t)(b * NN + i0) * HH + h * DH;
    const float* Kb = g_K + (size_t)(b * NN + j0) * HH + h * DH;

    #pragma unroll
    for (int it = 0; it < 4; it++) {
        int f   = tid + it * 256;
        int row = f >> 4;
        int dq  = f & 15;
        float4 qv = *(const float4*)&Qb[(size_t)row * HH + dq * 4];
        As[row * 65 + dq * 4 + 0] = qv.x;
        As[row * 65 + dq * 4 + 1] = qv.y;
        As[row * 65 + dq * 4 + 2] = qv.z;
        As[row * 65 + dq * 4 + 3] = qv.w;
        float4 kv = *(const float4*)&Kb[(size_t)row * HH + dq * 4];
        Bs[row * 65 + dq * 4 + 0] = kv.x;
        Bs[row * 65 + dq * 4 + 1] = kv.y;
        Bs[row * 65 + dq * 4 + 2] = kv.z;
        Bs[row * 65 + dq * 4 + 3] = kv.w;
    }
    __syncthreads();

    float acc[4][4] = {};
    #pragma unroll 8
    for (int k = 0; k < 64; k++) {
        float a[4], bv[4];
        #pragma unroll
        for (int ii = 0; ii < 4; ii++) a[ii] = As[(ty * 4 + ii) * 65 + k];
        #pragma unroll
        for (int jj = 0; jj < 4; jj++) bv[jj] = Bs[(tx * 4 + jj) * 65 + k];
        #pragma unroll
        for (int ii = 0; ii < 4; ii++)
            #pragma unroll
            for (int jj = 0; jj < 4; jj++)
                acc[ii][jj] = fmaf(a[ii], bv[jj], acc[ii][jj]);
    }

    const float cwh = cw[h], cbh = cb[h];
    const float* taub = tau + (size_t)b * NN;
    float4 tjv = *(const float4*)&taub[j0 + tx * 4];
    float tj[4] = {tjv.x, tjv.y, tjv.z, tjv.w};

    #pragma unroll
    for (int ii = 0; ii < 4; ii++) {
        int gi = i0 + ty * 4 + ii;
        float ti = taub[gi];
        int4 av = *(const int4*)&adj[(size_t)gi * NN + j0 + tx * 4];
        float4 o;
        o.x = (av.x == 0) ? NEG_INF : fmaf(acc[ii][0], 0.125f, fmaf(ti * tj[0], cwh, cbh));
        o.y = (av.y == 0) ? NEG_INF : fmaf(acc[ii][1], 0.125f, fmaf(ti * tj[1], cwh, cbh));
        o.z = (av.z == 0) ? NEG_INF : fmaf(acc[ii][2], 0.125f, fmaf(ti * tj[2], cwh, cbh));
        o.w = (av.w == 0) ? NEG_INF : fmaf(acc[ii][3], 0.125f, fmaf(ti * tj[3], cwh, cbh));
        *(float4*)&g_S[((size_t)bh * NN + gi) * NN + j0 + tx * 4] = o;
    }
}

// ---------------------------------------------------------------------------
// Softmax + head-mean: one CTA per (b,i). Normalizes S in place (-> P),
// accumulates mean over heads into out_am[b,i,:].
// ---------------------------------------------------------------------------
__device__ __forceinline__ float warpMax(float v) {
    #pragma unroll
    for (int o = 16; o > 0; o >>= 1) v = fmaxf(v, __shfl_xor_sync(0xffffffffu, v, o));
    return v;
}
__device__ __forceinline__ float warpSum(float v) {
    #pragma unroll
    for (int o = 16; o > 0; o >>= 1) v += __shfl_xor_sync(0xffffffffu, v, o);
    return v;
}

__global__ __launch_bounds__(256) void softmax_kernel(float* __restrict__ out_am)
{
    const int bi = blockIdx.x;
    const int b = bi >> 12, i = bi & 4095;
    const int tid = threadIdx.x;
    const int lane = tid & 31, wid = tid >> 5;
    __shared__ float red[8];

    float macc[16];
    #pragma unroll
    for (int r = 0; r < 16; r++) macc[r] = 0.f;

    for (int h = 0; h < NHEADS; h++) {
        float* row = g_S + ((size_t)((b * 4 + h) * NN) + i) * NN;
        float p[16];
        #pragma unroll
        for (int r = 0; r < 4; r++) {
            float4 v = *(const float4*)&row[(tid + r * 256) * 4];
            p[r * 4 + 0] = v.x; p[r * 4 + 1] = v.y;
            p[r * 4 + 2] = v.z; p[r * 4 + 3] = v.w;
        }
        // row max
        float m = p[0];
        #pragma unroll
        for (int r = 1; r < 16; r++) m = fmaxf(m, p[r]);
        m = warpMax(m);
        if (lane == 0) red[wid] = m;
        __syncthreads();
        if (wid == 0) {
            float x = (lane < 8) ? red[lane] : NEG_INF;
            x = warpMax(x);
            if (lane == 0) red[0] = x;
        }
        __syncthreads();
        m = red[0];
        __syncthreads();
        // exp & sum
        float s = 0.f;
        #pragma unroll
        for (int r = 0; r < 16; r++) { p[r] = __expf(p[r] - m); s += p[r]; }
        s = warpSum(s);
        if (lane == 0) red[wid] = s;
        __syncthreads();
        if (wid == 0) {
            float x = (lane < 8) ? red[lane] : 0.f;
            x = warpSum(x);
            if (lane == 0) red[0] = x;
        }
        __syncthreads();
        float inv = 1.0f / red[0];
        __syncthreads();
        // normalize, accumulate mean, write back
        #pragma unroll
        for (int r = 0; r < 16; r++) { p[r] *= inv; macc[r] += p[r]; }
        #pragma unroll
        for (int r = 0; r < 4; r++) {
            float4 v = make_float4(p[r*4+0], p[r*4+1], p[r*4+2], p[r*4+3]);
            *(float4*)&row[(tid + r * 256) * 4] = v;
        }
    }

    float* am = out_am + ((size_t)(b * NN) + i) * NN;
    #pragma unroll
    for (int r = 0; r < 4; r++) {
        float4 v = make_float4(macc[r*4+0] * 0.25f, macc[r*4+1] * 0.25f,
                               macc[r*4+2] * 0.25f, macc[r*4+3] * 0.25f);
        *(float4*)&am[(tid + r * 256) * 4] = v;
    }
}

// ---------------------------------------------------------------------------
// PV: AV[b,i, h*64+d] = sum_j P[b,h,i,j] * V[b,j, h*64+d]
// grid (N/64, B*NHEADS), 256 thr, k-loop over N
// ---------------------------------------------------------------------------
__global__ __launch_bounds__(256) void pv_kernel()
{
    __shared__ float Ps[64 * 65];
    __shared__ float Vs[64 * 65];
    const int tid = threadIdx.x;
    const int tx = tid & 15, ty = tid >> 4;
    const int bh = blockIdx.y;
    const int b = bh >> 2, h = bh & 3;
    const int i0 = blockIdx.x * 64;

    const float* Pb = g_S + ((size_t)bh * NN + i0) * NN;
    const float* Vb = g_V + (size_t)(b * NN) * HH + h * DH;

    float acc[4][4] = {};

    for (int k0 = 0; k0 < NN; k0 += 64) {
        __syncthreads();
        #pragma unroll
        for (int it = 0; it < 4; it++) {
            int f   = tid + it * 256;
            int row = f >> 4;
            int dq  = f & 15;
            float4 pv = *(const float4*)&Pb[(size_t)row * NN + k0 + dq * 4];
            Ps[row * 65 + dq * 4 + 0] = pv.x;
            Ps[row * 65 + dq * 4 + 1] = pv.y;
            Ps[row * 65 + dq * 4 + 2] = pv.z;
            Ps[row * 65 + dq * 4 + 3] = pv.w;
            float4 vv = *(const float4*)&Vb[(size_t)(k0 + row) * HH + dq * 4];
            Vs[row * 65 + dq * 4 + 0] = vv.x;
            Vs[row * 65 + dq * 4 + 1] = vv.y;
            Vs[row * 65 + dq * 4 + 2] = vv.z;
            Vs[row * 65 + dq * 4 + 3] = vv.w;
        }
        __syncthreads();
        #pragma unroll 8
        for (int k = 0; k < 64; k++) {
            float a[4], bv[4];
            #pragma unroll
            for (int ii = 0; ii < 4; ii++) a[ii] = Ps[(ty * 4 + ii) * 65 + k];
            #pragma unroll
            for (int jj = 0; jj < 4; jj++) bv[jj] = Vs[k * 65 + tx * 4 + jj];
            #pragma unroll
            for (int ii = 0; ii < 4; ii++)
                #pragma unroll
                for (int jj = 0; jj < 4; jj++)
                    acc[ii][jj] = fmaf(a[ii], bv[jj], acc[ii][jj]);
        }
    }

    #pragma unroll
    for (int ii = 0; ii < 4; ii++) {
        float4 o = make_float4(acc[ii][0], acc[ii][1], acc[ii][2], acc[ii][3]);
        *(float4*)&g_AV[(size_t)(b * NN + i0 + ty * 4 + ii) * HH + h * DH + tx * 4] = o;
    }
}

// ---------------------------------------------------------------------------
// Launch
// inputs: 0:h 1:tau 2:adj_mask 3:Wq 4:bq 5:Wk 6:bk 7:Wv 8:bv 9:cw 10:cb 11:Wo 12:bo
// output: [h_out (B,N,256)] ++ [attn_mean (B,N,N)]
// ---------------------------------------------------------------------------
extern "C" void kernel_launch(void* const* d_in, const int* in_sizes, int n_in,
                              void* d_out, int out_size)
{
    const float* h_in = (const float*)d_in[0];
    const float* tau  = (const float*)d_in[1];
    const int*   adj  = (const int*)  d_in[2];
    const float* Wq   = (const float*)d_in[3];
    const float* bq   = (const float*)d_in[4];
    const float* Wk   = (const float*)d_in[5];
    const float* bk   = (const float*)d_in[6];
    const float* Wv   = (const float*)d_in[7];
    const float* bv   = (const float*)d_in[8];
    const float* cw   = (const float*)d_in[9];
    const float* cb   = (const float*)d_in[10];
    const float* Wo   = (const float*)d_in[11];
    const float* bo   = (const float*)d_in[12];

    float* out_h  = (float*)d_out;
    float* out_am = out_h + (size_t)MTOT * HH;

    void *pQ, *pK, *pV, *pAV;
    cudaGetSymbolAddress(&pQ,  g_Q);
    cudaGetSymbolAddress(&pK,  g_K);
    cudaGetSymbolAddress(&pV,  g_V);
    cudaGetSymbolAddress(&pAV, g_AV);

    dim3 gProj(MTOT / 64, HH / 64);
    gemm_xwt<<<gProj, 256>>>(h_in, Wq, bq, (float*)pQ);
    gemm_xwt<<<gProj, 256>>>(h_in, Wk, bk, (float*)pK);
    gemm_xwt<<<gProj, 256>>>(h_in, Wv, bv, (float*)pV);

    scores_kernel<<<dim3(NN / 64, NN / 64, BB * NHEADS), 256>>>(tau, adj, cw, cb);

    softmax_kernel<<<BB * NN, 256>>>(out_am);

    pv_kernel<<<dim3(NN / 64, BB * NHEADS), 256>>>();

    gemm_xwt<<<gProj, 256>>>((const float*)pAV, Wo, bo, out_h);
}

// round 3
// speedup vs baseline: 2.0615x; 2.0615x over previous
#include <cuda_runtime.h>
#include <cuda_bf16.h>
#include <cstdint>

#define BB 2
#define NN 4096
#define HH 256
#define NHEADS 4
#define DH 64
#define MTOT (BB*NN)          // 8192 rows

// ---------------------------------------------------------------------------
// Scratch (__device__ globals — no cudaMalloc allowed)
// ---------------------------------------------------------------------------
__device__ float g_Q [(size_t)MTOT * HH];          // 8 MB
__device__ float g_K [(size_t)MTOT * HH];          // 8 MB
__device__ float g_V [(size_t)MTOT * HH];          // 8 MB
__device__ float g_AV[(size_t)MTOT * HH];          // 8 MB
__device__ float g_S [134217728ULL];               // (B*NHEADS*N)*N = 512 MB

#define NEG_INF __int_as_float(0xff800000)

// ---------------------------------------------------------------------------
// MMA helpers (bf16 m16n8k16, f32 accumulate)
// ---------------------------------------------------------------------------
__device__ __forceinline__ uint32_t smem_u32(const void* p) {
    return (uint32_t)__cvta_generic_to_shared(p);
}

__device__ __forceinline__ void ldsm_x4(uint32_t addr, uint32_t& r0, uint32_t& r1,
                                        uint32_t& r2, uint32_t& r3) {
    asm volatile("ldmatrix.sync.aligned.m8n8.x4.shared.b16 {%0,%1,%2,%3}, [%4];"
                 : "=r"(r0), "=r"(r1), "=r"(r2), "=r"(r3) : "r"(addr));
}
__device__ __forceinline__ void ldsm_x4_t(uint32_t addr, uint32_t& r0, uint32_t& r1,
                                          uint32_t& r2, uint32_t& r3) {
    asm volatile("ldmatrix.sync.aligned.m8n8.x4.trans.shared.b16 {%0,%1,%2,%3}, [%4];"
                 : "=r"(r0), "=r"(r1), "=r"(r2), "=r"(r3) : "r"(addr));
}
__device__ __forceinline__ void mma_bf16(float* d, const uint32_t* a, const uint32_t* b) {
    asm volatile(
        "mma.sync.aligned.m16n8k16.row.col.f32.bf16.bf16.f32 "
        "{%0,%1,%2,%3}, {%4,%5,%6,%7}, {%8,%9}, {%0,%1,%2,%3};"
        : "+f"(d[0]), "+f"(d[1]), "+f"(d[2]), "+f"(d[3])
        : "r"(a[0]), "r"(a[1]), "r"(a[2]), "r"(a[3]), "r"(b[0]), "r"(b[1]));
}

// split fp32 -> (hi, lo) bf16
__device__ __forceinline__ void split_bf16(float x, __nv_bfloat16& h, __nv_bfloat16& l) {
    h = __float2bfloat16_rn(x);
    l = __float2bfloat16_rn(x - __bfloat162float(h));
}

// ---------------------------------------------------------------------------
// GEMM (fp32): Y[m,o] = sum_k X[m,k] * W[o,k] + bias[o]
// ---------------------------------------------------------------------------
__global__ __launch_bounds__(256) void gemm_xwt(
    const float* __restrict__ X, const float* __restrict__ W,
    const float* __restrict__ bias, float* __restrict__ Y)
{
    __shared__ float Xs[64 * 65];
    __shared__ float Ws[64 * 65];
    const int tid = threadIdx.x;
    const int tx = tid & 15, ty = tid >> 4;
    const int m0 = blockIdx.x * 64, n0 = blockIdx.y * 64;

    float acc[4][4] = {};

    for (int k0 = 0; k0 < HH; k0 += 64) {
        __syncthreads();
        #pragma unroll
        for (int it = 0; it < 4; it++) {
            int f   = tid + it * 256;
            int row = f >> 4;
            int dq  = f & 15;
            float4 xv = *(const float4*)&X[(size_t)(m0 + row) * HH + k0 + dq * 4];
            Xs[row * 65 + dq * 4 + 0] = xv.x;
            Xs[row * 65 + dq * 4 + 1] = xv.y;
            Xs[row * 65 + dq * 4 + 2] = xv.z;
            Xs[row * 65 + dq * 4 + 3] = xv.w;
            float4 wv = *(const float4*)&W[(size_t)(n0 + row) * HH + k0 + dq * 4];
            Ws[row * 65 + dq * 4 + 0] = wv.x;
            Ws[row * 65 + dq * 4 + 1] = wv.y;
            Ws[row * 65 + dq * 4 + 2] = wv.z;
            Ws[row * 65 + dq * 4 + 3] = wv.w;
        }
        __syncthreads();
        #pragma unroll 8
        for (int k = 0; k < 64; k++) {
            float a[4], b[4];
            #pragma unroll
            for (int ii = 0; ii < 4; ii++) a[ii] = Xs[(ty * 4 + ii) * 65 + k];
            #pragma unroll
            for (int jj = 0; jj < 4; jj++) b[jj] = Ws[(tx * 4 + jj) * 65 + k];
            #pragma unroll
            for (int ii = 0; ii < 4; ii++)
                #pragma unroll
                for (int jj = 0; jj < 4; jj++)
                    acc[ii][jj] = fmaf(a[ii], b[jj], acc[ii][jj]);
        }
    }

    float4 bv = *(const float4*)&bias[n0 + tx * 4];
    #pragma unroll
    for (int ii = 0; ii < 4; ii++) {
        float4 o;
        o.x = acc[ii][0] + bv.x;
        o.y = acc[ii][1] + bv.y;
        o.z = acc[ii][2] + bv.z;
        o.w = acc[ii][3] + bv.w;
        *(float4*)&Y[(size_t)(m0 + ty * 4 + ii) * HH + n0 + tx * 4] = o;
    }
}

// ---------------------------------------------------------------------------
// Scores (tensor-core): S[b,h,i,j] = (Q.K)/8 + tau_i*tau_j*cw[h] + cb[h], masked
// tile 128x128, k=64, split-precision 3-pass bf16 MMA.
// grid: x=bh(8), y=jt(32), z=it(32); 256 threads
// ---------------------------------------------------------------------------
#define LDQ 136   // bf16 stride: 64 hi | 64 lo | 8 pad

__global__ __launch_bounds__(256) void scores_mma(
    const float* __restrict__ tau, const int* __restrict__ adj,
    const float* __restrict__ cw, const float* __restrict__ cb)
{
    extern __shared__ __nv_bfloat16 sm[];
    __nv_bfloat16* Qs = sm;                 // [128][LDQ]
    __nv_bfloat16* Ks = sm + 128 * LDQ;     // [128][LDQ]

    const int tid  = threadIdx.x;
    const int lane = tid & 31, warp = tid >> 5;
    const int wm = warp >> 2, wn = warp & 3;      // 2 x 4 warp grid
    const int bh = blockIdx.x;
    const int b = bh >> 2, h = bh & 3;
    const int j0 = blockIdx.y * 128, i0 = blockIdx.z * 128;

    const float* Qb = g_Q + (size_t)(b * NN + i0) * HH + h * DH;
    const float* Kb = g_K + (size_t)(b * NN + j0) * HH + h * DH;

    // load + split-convert Q and K tiles (128 x 64 fp32 each)
    #pragma unroll
    for (int it = 0; it < 8; it++) {
        int f   = tid + it * 256;           // 0..2047 float4 slots
        int row = f >> 4;
        int kq  = f & 15;
        float4 qv = *(const float4*)&Qb[(size_t)row * HH + kq * 4];
        __nv_bfloat16 h0, l0, h1, l1, h2, l2, h3, l3;
        split_bf16(qv.x, h0, l0); split_bf16(qv.y, h1, l1);
        split_bf16(qv.z, h2, l2); split_bf16(qv.w, h3, l3);
        __nv_bfloat16* qh = Qs + row * LDQ + kq * 4;
        qh[0] = h0; qh[1] = h1; qh[2] = h2; qh[3] = h3;
        __nv_bfloat16* ql = qh + 64;
        ql[0] = l0; ql[1] = l1; ql[2] = l2; ql[3] = l3;

        float4 kv = *(const float4*)&Kb[(size_t)row * HH + kq * 4];
        split_bf16(kv.x, h0, l0); split_bf16(kv.y, h1, l1);
        split_bf16(kv.z, h2, l2); split_bf16(kv.w, h3, l3);
        __nv_bfloat16* kh = Ks + row * LDQ + kq * 4;
        kh[0] = h0; kh[1] = h1; kh[2] = h2; kh[3] = h3;
        __nv_bfloat16* kl = kh + 64;
        kl[0] = l0; kl[1] = l1; kl[2] = l2; kl[3] = l3;
    }
    __syncthreads();

    float acc[4][4][4] = {};
    const uint32_t qbase = smem_u32(Qs);
    const uint32_t kbase = smem_u32(Ks);

    #pragma unroll
    for (int pass = 0; pass < 3; pass++) {
        const int aOff = (pass == 1) ? 64 : 0;
        const int bOff = (pass == 2) ? 64 : 0;
        #pragma unroll
        for (int ks = 0; ks < 4; ks++) {
            const int kc = ks * 16;
            uint32_t a[4][4];
            #pragma unroll
            for (int mt = 0; mt < 4; mt++) {
                int r = wm * 64 + mt * 16 + (lane & 15);
                int c = aOff + kc + ((lane >> 4) << 3);
                ldsm_x4(qbase + (uint32_t)(r * LDQ + c) * 2,
                        a[mt][0], a[mt][1], a[mt][2], a[mt][3]);
            }
            uint32_t bf[4][2];
            #pragma unroll
            for (int hf = 0; hf < 2; hf++) {
                int r = wn * 32 + hf * 16 + ((lane >> 4) << 3) + (lane & 7);
                int c = bOff + kc + (lane & 8);
                uint32_t r0, r1, r2, r3;
                ldsm_x4(kbase + (uint32_t)(r * LDQ + c) * 2, r0, r1, r2, r3);
                bf[hf * 2 + 0][0] = r0; bf[hf * 2 + 0][1] = r1;
                bf[hf * 2 + 1][0] = r2; bf[hf * 2 + 1][1] = r3;
            }
            #pragma unroll
            for (int mt = 0; mt < 4; mt++)
                #pragma unroll
                for (int nt = 0; nt < 4; nt++)
                    mma_bf16(acc[mt][nt], a[mt], bf[nt]);
        }
    }

    // epilogue: scale, credibility bias, adjacency mask, store
    const float cwh = cw[h], cbh = cb[h];
    const float* taub = tau + (size_t)b * NN;
    const int g  = lane >> 2;
    const int t2 = (lane & 3) * 2;

    float2 tj[4];
    #pragma unroll
    for (int nt = 0; nt < 4; nt++)
        tj[nt] = *(const float2*)&taub[j0 + wn * 32 + nt * 8 + t2];

    #pragma unroll
    for (int mt = 0; mt < 4; mt++) {
        const int r0 = i0 + wm * 64 + mt * 16 + g;
        const int r1 = r0 + 8;
        const float ti0 = taub[r0], ti1 = taub[r1];
        #pragma unroll
        for (int nt = 0; nt < 4; nt++) {
            const int col = j0 + wn * 32 + nt * 8 + t2;
            int2 a0 = *(const int2*)&adj[(size_t)r0 * NN + col];
            int2 a1 = *(const int2*)&adj[(size_t)r1 * NN + col];
            float* ac = acc[mt][nt];
            float2 o0, o1;
            o0.x = a0.x ? fmaf(ac[0], 0.125f, fmaf(ti0 * tj[nt].x, cwh, cbh)) : NEG_INF;
            o0.y = a0.y ? fmaf(ac[1], 0.125f, fmaf(ti0 * tj[nt].y, cwh, cbh)) : NEG_INF;
            o1.x = a1.x ? fmaf(ac[2], 0.125f, fmaf(ti1 * tj[nt].x, cwh, cbh)) : NEG_INF;
            o1.y = a1.y ? fmaf(ac[3], 0.125f, fmaf(ti1 * tj[nt].y, cwh, cbh)) : NEG_INF;
            *(float2*)&g_S[((size_t)bh * NN + r0) * NN + col] = o0;
            *(float2*)&g_S[((size_t)bh * NN + r1) * NN + col] = o1;
        }
    }
}

// ---------------------------------------------------------------------------
// Softmax + head-mean (unchanged)
// ---------------------------------------------------------------------------
__device__ __forceinline__ float warpMax(float v) {
    #pragma unroll
    for (int o = 16; o > 0; o >>= 1) v = fmaxf(v, __shfl_xor_sync(0xffffffffu, v, o));
    return v;
}
__device__ __forceinline__ float warpSum(float v) {
    #pragma unroll
    for (int o = 16; o > 0; o >>= 1) v += __shfl_xor_sync(0xffffffffu, v, o);
    return v;
}

__global__ __launch_bounds__(256) void softmax_kernel(float* __restrict__ out_am)
{
    const int bi = blockIdx.x;
    const int b = bi >> 12, i = bi & 4095;
    const int tid = threadIdx.x;
    const int lane = tid & 31, wid = tid >> 5;
    __shared__ float red[8];

    float macc[16];
    #pragma unroll
    for (int r = 0; r < 16; r++) macc[r] = 0.f;

    for (int h = 0; h < NHEADS; h++) {
        float* row = g_S + ((size_t)((b * 4 + h) * NN) + i) * NN;
        float p[16];
        #pragma unroll
        for (int r = 0; r < 4; r++) {
            float4 v = *(const float4*)&row[(tid + r * 256) * 4];
            p[r * 4 + 0] = v.x; p[r * 4 + 1] = v.y;
            p[r * 4 + 2] = v.z; p[r * 4 + 3] = v.w;
        }
        float m = p[0];
        #pragma unroll
        for (int r = 1; r < 16; r++) m = fmaxf(m, p[r]);
        m = warpMax(m);
        if (lane == 0) red[wid] = m;
        __syncthreads();
        if (wid == 0) {
            float x = (lane < 8) ? red[lane] : NEG_INF;
            x = warpMax(x);
            if (lane == 0) red[0] = x;
        }
        __syncthreads();
        m = red[0];
        __syncthreads();
        float s = 0.f;
        #pragma unroll
        for (int r = 0; r < 16; r++) { p[r] = __expf(p[r] - m); s += p[r]; }
        s = warpSum(s);
        if (lane == 0) red[wid] = s;
        __syncthreads();
        if (wid == 0) {
            float x = (lane < 8) ? red[lane] : 0.f;
            x = warpSum(x);
            if (lane == 0) red[0] = x;
        }
        __syncthreads();
        float inv = 1.0f / red[0];
        __syncthreads();
        #pragma unroll
        for (int r = 0; r < 16; r++) { p[r] *= inv; macc[r] += p[r]; }
        #pragma unroll
        for (int r = 0; r < 4; r++) {
            float4 v = make_float4(p[r*4+0], p[r*4+1], p[r*4+2], p[r*4+3]);
            *(float4*)&row[(tid + r * 256) * 4] = v;
        }
    }

    float* am = out_am + ((size_t)(b * NN) + i) * NN;
    #pragma unroll
    for (int r = 0; r < 4; r++) {
        float4 v = make_float4(macc[r*4+0] * 0.25f, macc[r*4+1] * 0.25f,
                               macc[r*4+2] * 0.25f, macc[r*4+3] * 0.25f);
        *(float4*)&am[(tid + r * 256) * 4] = v;
    }
}

// ---------------------------------------------------------------------------
// PV (tensor-core): AV[b,i,h*64+d] = sum_j P[bh,i,j] * V[b,j,h*64+d]
// tile 128(i) x 64(d), k-loop j in steps of 64, split-precision 3-pass.
// grid: x=it(32), y=bh(8); 256 threads
// ---------------------------------------------------------------------------
#define LDV 72   // V tile stride (64 d + 8 pad), rows = j (hi: 0-63, lo: 64-127)

__global__ __launch_bounds__(256) void pv_mma()
{
    extern __shared__ __nv_bfloat16 sm[];
    __nv_bfloat16* Ps = sm;                 // [128 i][LDQ]  (j: 64 hi | 64 lo)
    __nv_bfloat16* Vs = sm + 128 * LDQ;     // [128 j(hi|lo)][LDV]

    const int tid  = threadIdx.x;
    const int lane = tid & 31, warp = tid >> 5;
    const int wm = warp >> 1, wn = warp & 1;      // 4 x 2 warp grid (32x32 each)
    const int bh = blockIdx.y;
    const int b = bh >> 2, h = bh & 3;
    const int i0 = blockIdx.x * 128;

    const float* Pb = g_S + ((size_t)bh * NN + i0) * NN;
    const float* Vb = g_V + (size_t)(b * NN) * HH + h * DH;

    float acc[2][4][4] = {};
    const uint32_t pbase = smem_u32(Ps);
    const uint32_t vbase = smem_u32(Vs);

    for (int jt = 0; jt < NN; jt += 64) {
        __syncthreads();
        // load P tile 128 x 64 fp32, split to bf16 hi/lo along j
        #pragma unroll
        for (int it = 0; it < 8; it++) {
            int f   = tid + it * 256;
            int row = f >> 4;
            int jq  = f & 15;
            float4 pv = *(const float4*)&Pb[(size_t)row * NN + jt + jq * 4];
            __nv_bfloat16 h0, l0, h1, l1, h2, l2, h3, l3;
            split_bf16(pv.x, h0, l0); split_bf16(pv.y, h1, l1);
            split_bf16(pv.z, h2, l2); split_bf16(pv.w, h3, l3);
            __nv_bfloat16* ph = Ps + row * LDQ + jq * 4;
            ph[0] = h0; ph[1] = h1; ph[2] = h2; ph[3] = h3;
            __nv_bfloat16* pl = ph + 64;
            pl[0] = l0; pl[1] = l1; pl[2] = l2; pl[3] = l3;
        }
        // load V tile 64(j) x 64(d) fp32, split to bf16; rows j hi at [0,64), lo at [64,128)
        #pragma unroll
        for (int it = 0; it < 4; it++) {
            int f  = tid + it * 256;
            int jr = f >> 4;
            int dq = f & 15;
            float4 vv = *(const float4*)&Vb[(size_t)(jt + jr) * HH + dq * 4];
            __nv_bfloat16 h0, l0, h1, l1, h2, l2, h3, l3;
            split_bf16(vv.x, h0, l0); split_bf16(vv.y, h1, l1);
            split_bf16(vv.z, h2, l2); split_bf16(vv.w, h3, l3);
            __nv_bfloat16* vh = Vs + jr * LDV + dq * 4;
            vh[0] = h0; vh[1] = h1; vh[2] = h2; vh[3] = h3;
            __nv_bfloat16* vl = vh + 64 * LDV;
            vl[0] = l0; vl[1] = l1; vl[2] = l2; vl[3] = l3;
        }
        __syncthreads();

        #pragma unroll
        for (int pass = 0; pass < 3; pass++) {
            const int aOff = (pass == 1) ? 64 : 0;   // P lo
            const int bOff = (pass == 2) ? 64 : 0;   // V lo (row offset)
            #pragma unroll
            for (int ks = 0; ks < 4; ks++) {
                const int kc = ks * 16;
                uint32_t a[2][4];
                #pragma unroll
                for (int mt = 0; mt < 2; mt++) {
                    int r = wm * 32 + mt * 16 + (lane & 15);
                    int c = aOff + kc + ((lane >> 4) << 3);
                    ldsm_x4(pbase + (uint32_t)(r * LDQ + c) * 2,
                            a[mt][0], a[mt][1], a[mt][2], a[mt][3]);
                }
                uint32_t bf[4][2];
                #pragma unroll
                for (int hf = 0; hf < 2; hf++) {
                    int r = bOff + kc + (lane & 7) + ((lane & 8) ? 8 : 0);
                    int c = wn * 32 + hf * 16 + ((lane >> 4) << 3);
                    uint32_t r0, r1, r2, r3;
                    ldsm_x4_t(vbase + (uint32_t)(r * LDV + c) * 2, r0, r1, r2, r3);
                    bf[hf * 2 + 0][0] = r0; bf[hf * 2 + 0][1] = r1;
                    bf[hf * 2 + 1][0] = r2; bf[hf * 2 + 1][1] = r3;
                }
                #pragma unroll
                for (int mt = 0; mt < 2; mt++)
                    #pragma unroll
                    for (int nt = 0; nt < 4; nt++)
                        mma_bf16(acc[mt][nt], a[mt], bf[nt]);
            }
        }
    }

    const int g  = lane >> 2;
    const int t2 = (lane & 3) * 2;
    #pragma unroll
    for (int mt = 0; mt < 2; mt++) {
        const int r0 = i0 + wm * 32 + mt * 16 + g;
        const int r1 = r0 + 8;
        #pragma unroll
        for (int nt = 0; nt < 4; nt++) {
            const int d = wn * 32 + nt * 8 + t2;
            float* ac = acc[mt][nt];
            *(float2*)&g_AV[(size_t)(b * NN + r0) * HH + h * DH + d] = make_float2(ac[0], ac[1]);
            *(float2*)&g_AV[(size_t)(b * NN + r1) * HH + h * DH + d] = make_float2(ac[2], ac[3]);
        }
    }
}

// ---------------------------------------------------------------------------
// Launch
// inputs: 0:h 1:tau 2:adj_mask 3:Wq 4:bq 5:Wk 6:bk 7:Wv 8:bv 9:cw 10:cb 11:Wo 12:bo
// ---------------------------------------------------------------------------
extern "C" void kernel_launch(void* const* d_in, const int* in_sizes, int n_in,
                              void* d_out, int out_size)
{
    const float* h_in = (const float*)d_in[0];
    const float* tau  = (const float*)d_in[1];
    const int*   adj  = (const int*)  d_in[2];
    const float* Wq   = (const float*)d_in[3];
    const float* bq   = (const float*)d_in[4];
    const float* Wk   = (const float*)d_in[5];
    const float* bk   = (const float*)d_in[6];
    const float* Wv   = (const float*)d_in[7];
    const float* bv   = (const float*)d_in[8];
    const float* cw   = (const float*)d_in[9];
    const float* cb   = (const float*)d_in[10];
    const float* Wo   = (const float*)d_in[11];
    const float* bo   = (const float*)d_in[12];

    float* out_h  = (float*)d_out;
    float* out_am = out_h + (size_t)MTOT * HH;

    void *pQ, *pK, *pV, *pAV;
    cudaGetSymbolAddress(&pQ,  g_Q);
    cudaGetSymbolAddress(&pK,  g_K);
    cudaGetSymbolAddress(&pV,  g_V);
    cudaGetSymbolAddress(&pAV, g_AV);

    const int smem_scores = 2 * 128 * LDQ * 2;             // 69632 B
    const int smem_pv     = (128 * LDQ + 128 * LDV) * 2;   // 53248 B
    cudaFuncSetAttribute(scores_mma, cudaFuncAttributeMaxDynamicSharedMemorySize, smem_scores);
    cudaFuncSetAttribute(pv_mma,     cudaFuncAttributeMaxDynamicSharedMemorySize, smem_pv);

    dim3 gProj(MTOT / 64, HH / 64);
    gemm_xwt<<<gProj, 256>>>(h_in, Wq, bq, (float*)pQ);
    gemm_xwt<<<gProj, 256>>>(h_in, Wk, bk, (float*)pK);
    gemm_xwt<<<gProj, 256>>>(h_in, Wv, bv, (float*)pV);

    scores_mma<<<dim3(BB * NHEADS, NN / 128, NN / 128), 256, smem_scores>>>(tau, adj, cw, cb);

    softmax_kernel<<<BB * NN, 256>>>(out_am);

    pv_mma<<<dim3(NN / 128, BB * NHEADS), 256, smem_pv>>>();

    gemm_xwt<<<gProj, 256>>>((const float*)pAV, Wo, bo, out_h);
}